// round 9
// baseline (speedup 1.0000x reference)
#include <cuda_runtime.h>
#include <cuda_fp16.h>
#include <math.h>

#define D 128
#define MAXN 10000
#define MAXE 640000

// Scratch (no allocation allowed -> __device__ globals)
// g_deg is zeroed by mega_kernel at the end of each call (zero-init at load),
// so no zero pass is needed.
__device__ int    g_deg[MAXN];
__device__ float  g_deginv[MAXN];
__device__ int    g_start[MAXN];            // exclusive prefix of deg
__device__ int    g_cursor[MAXN];           // running fill cursors
__device__ __align__(16) int2    g_edge[MAXE];       // CSR: {src, coef_bits}
__device__ __align__(16) __half2 g_xh[MAXN * (D/2)]; // fp16 copy of x

// ---------------------------------------------------------------------------
// Pass 1: in-degree histogram + fp16 conversion of x (fused; both are cheap
// and independent).  edge_index is int32.
// ---------------------------------------------------------------------------
__global__ void deg_cvt_kernel(const int* __restrict__ ei,
                               const float* __restrict__ x,
                               int E, int n_h2) {
    int i = blockIdx.x * blockDim.x + threadIdx.x;
    if (i < E) {
        atomicAdd(&g_deg[ei[E + i]], 1);
    }
    for (int j = i; j < n_h2; j += gridDim.x * blockDim.x) {
        float2 f = reinterpret_cast<const float2*>(x)[j];
        g_xh[j] = __floats2half2_rn(f.x, f.y);
    }
}

// ---------------------------------------------------------------------------
// Pass 2: single-block exclusive scan over deg -> start, cursor; also deginv.
// shfl-based: per-thread chunk sums -> warp scan -> warp-0 scan -> add back.
// ---------------------------------------------------------------------------
__global__ void scan_kernel(int N) {
    __shared__ int s_wsum[32];
    const int tid  = threadIdx.x;
    const int lane = tid & 31;
    const int wid  = tid >> 5;
    const int CH   = (N + 1023) / 1024;
    const int base = tid * CH;

    int sum = 0;
    for (int j = 0; j < CH; j++) {
        int i = base + j;
        if (i < N) sum += g_deg[i];
    }

    // inclusive warp scan of per-thread sums
    int inc = sum;
    #pragma unroll
    for (int off = 1; off < 32; off <<= 1) {
        int v = __shfl_up_sync(0xFFFFFFFF, inc, off);
        if (lane >= off) inc += v;
    }
    if (lane == 31) s_wsum[wid] = inc;
    __syncthreads();

    if (wid == 0) {
        int w = s_wsum[lane];
        int wi = w;
        #pragma unroll
        for (int off = 1; off < 32; off <<= 1) {
            int v = __shfl_up_sync(0xFFFFFFFF, wi, off);
            if (lane >= off) wi += v;
        }
        s_wsum[lane] = wi - w;   // exclusive warp offsets
    }
    __syncthreads();

    int run = s_wsum[wid] + inc - sum;   // exclusive prefix for this thread
    for (int j = 0; j < CH; j++) {
        int i = base + j;
        if (i < N) {
            int d = g_deg[i];
            g_start[i]  = run;
            g_cursor[i] = run;
            g_deginv[i] = rsqrtf((float)d + 1.0f);
            run += d;
        }
    }
}

// ---------------------------------------------------------------------------
// Pass 3: fill CSR buckets. One int atomic + ONE 8B store per edge.
// ---------------------------------------------------------------------------
__global__ void fill_kernel(const int* __restrict__ ei,
                            const float* __restrict__ ew,
                            int E) {
    int e = blockIdx.x * blockDim.x + threadIdx.x;
    if (e < E) {
        int src = ei[e];
        int dst = ei[E + e];
        int pos = atomicAdd(&g_cursor[dst], 1);
        float coef = g_deginv[src] * ew[e];
        g_edge[pos] = make_int2(src, __float_as_int(coef));
    }
}

// ---------------------------------------------------------------------------
// Pass 4: mega kernel — gather (fp16 x) + residual + GEMM + GELU + LayerNorm.
// Block = 256 threads (8 warps) -> 8 rows.
//  Phase 1: warp w gathers row row0+w; lane l owns cols [4l,4l+4) (one 8B
//           half2x2 load per edge).  Also zeros g_deg[row] for the next call.
//  Phase 2: col = tid&127, half = tid>>7: GEMM over 4 rows.
//  Phase 3: GELU + LN.
// ---------------------------------------------------------------------------
__global__ void mega_kernel(const float* __restrict__ x,
                            const float* __restrict__ W,
                            const float* __restrict__ b,
                            const float* __restrict__ gamma,
                            const float* __restrict__ beta,
                            float* __restrict__ out,
                            int N) {
    __shared__ float s_a[8][D];
    __shared__ int   s_src[8][32];
    __shared__ float s_cf[8][32];
    __shared__ float s_sum[8][4];
    __shared__ float s_sq[8][4];

    const int tid  = threadIdx.x;
    const int wid  = tid >> 5;
    const int lane = tid & 31;
    const int row0 = blockIdx.x * 8;

    // ---- Phase 1: gather own row ----
    {
        const int row = row0 + wid;
        if (row < N) {
            const int s0   = g_start[row];
            const int dcnt = g_deg[row];
            if (lane == 0) g_deg[row] = 0;   // restore invariant for next call

            float4 acc = make_float4(0.f, 0.f, 0.f, 0.f);

            for (int base = 0; base < dcnt; base += 32) {
                int idx = base + lane;
                if (idx < dcnt) {
                    int2 em = g_edge[s0 + idx];
                    s_src[wid][lane] = em.x;
                    s_cf[wid][lane]  = __int_as_float(em.y);
                }
                __syncwarp();

                int m = dcnt - base;
                if (m > 32) m = 32;
                #pragma unroll 4
                for (int k = 0; k < m; k++) {
                    int   s = s_src[wid][k];
                    float c = s_cf[wid][k];
                    uint2 u = reinterpret_cast<const uint2*>(
                                  g_xh + (size_t)s * (D/2))[lane];
                    float2 f0 = __half22float2(*reinterpret_cast<__half2*>(&u.x));
                    float2 f1 = __half22float2(*reinterpret_cast<__half2*>(&u.y));
                    acc.x += f0.x * c; acc.y += f0.y * c;
                    acc.z += f1.x * c; acc.w += f1.y * c;
                }
                __syncwarp();
            }

            float di = g_deginv[row];
            float4 xr = reinterpret_cast<const float4*>(x + (size_t)row * D)[lane];
            float* pa = &s_a[wid][lane * 4];
            pa[0] = acc.x * di + xr.x;
            pa[1] = acc.y * di + xr.y;
            pa[2] = acc.z * di + xr.z;
            pa[3] = acc.w * di + xr.w;
        } else {
            float* pa = &s_a[wid][lane * 4];
            pa[0] = pa[1] = pa[2] = pa[3] = 0.f;
        }
    }
    __syncthreads();

    // ---- Phase 2: GEMM ----
    const int col  = tid & 127;
    const int half = tid >> 7;
    const int r0   = half * 4;

    float acc0 = b[col], acc1 = acc0, acc2 = acc0, acc3 = acc0;

    #pragma unroll 8
    for (int k = 0; k < D; k++) {
        float w = W[k * D + col];
        acc0 += s_a[r0 + 0][k] * w;
        acc1 += s_a[r0 + 1][k] * w;
        acc2 += s_a[r0 + 2][k] * w;
        acc3 += s_a[r0 + 3][k] * w;
    }

    float h[4] = {acc0, acc1, acc2, acc3};

    // exact gelu
    #pragma unroll
    for (int r = 0; r < 4; r++) {
        float v = h[r];
        h[r] = 0.5f * v * (1.0f + erff(v * 0.70710678118654752f));
    }

    // ---- Phase 3: LayerNorm ----
    float sum[4], sq[4];
    #pragma unroll
    for (int r = 0; r < 4; r++) { sum[r] = h[r]; sq[r] = h[r] * h[r]; }

    #pragma unroll
    for (int off = 16; off > 0; off >>= 1) {
        #pragma unroll
        for (int r = 0; r < 4; r++) {
            sum[r] += __shfl_xor_sync(0xFFFFFFFF, sum[r], off);
            sq[r]  += __shfl_xor_sync(0xFFFFFFFF, sq[r], off);
        }
    }
    const int wih = (tid >> 5) & 3;
    if (lane == 0) {
        #pragma unroll
        for (int r = 0; r < 4; r++) {
            s_sum[r0 + r][wih] = sum[r];
            s_sq[r0 + r][wih]  = sq[r];
        }
    }
    __syncthreads();

    float g = gamma[col], bt = beta[col];
    #pragma unroll
    for (int r = 0; r < 4; r++) {
        int rr = r0 + r;
        float s = s_sum[rr][0] + s_sum[rr][1] + s_sum[rr][2] + s_sum[rr][3];
        float q = s_sq[rr][0]  + s_sq[rr][1]  + s_sq[rr][2]  + s_sq[rr][3];
        float mu  = s * (1.0f / D);
        float var = q * (1.0f / D) - mu * mu;
        float rstd = rsqrtf(var + 1e-5f);
        int row = row0 + rr;
        if (row < N) {
            out[(size_t)row * D + col] = (h[r] - mu) * rstd * g + bt;
        }
    }
}

// ---------------------------------------------------------------------------
// Launch
// Inputs (metadata order): x, edge_index(int32), edge_weight, W, b, gamma, beta
// ---------------------------------------------------------------------------
extern "C" void kernel_launch(void* const* d_in, const int* in_sizes, int n_in,
                              void* d_out, int out_size) {
    const float* x     = (const float*)d_in[0];
    const int*   ei    = (const int*)d_in[1];
    const float* ew    = (const float*)d_in[2];
    const float* W     = (const float*)d_in[3];
    const float* b     = (const float*)d_in[4];
    const float* gamma = (const float*)d_in[5];
    const float* beta  = (const float*)d_in[6];
    float*       out   = (float*)d_out;

    const int N = in_sizes[0] / D;       // 10000
    const int E = in_sizes[2];           // 640000

    int n_h2 = N * (D / 2);              // 640000 half2 elements
    int work = (E > n_h2) ? E : n_h2;

    deg_cvt_kernel<<<(work + 255) / 256, 256>>>(ei, x, E, n_h2);
    scan_kernel<<<1, 1024>>>(N);                       // + deginv + cursors
    fill_kernel<<<(E + 255) / 256, 256>>>(ei, ew, E);
    mega_kernel<<<(N + 7) / 8, 256>>>(x, W, b, gamma, beta, out, N);
}

// round 11
// speedup vs baseline: 1.1796x; 1.1796x over previous
#include <cuda_runtime.h>
#include <math.h>

#define D 128
#define MAXN 10000
#define MAXE 640000

// Scratch (no allocation allowed -> __device__ globals)
// g_deg is zeroed by mega_kernel after use (zero-init at load), no zero pass.
__device__ int    g_deg[MAXN];
__device__ float  g_deginv[MAXN];
__device__ int    g_start[MAXN];            // exclusive prefix of deg
__device__ int    g_cursor[MAXN];           // running fill cursors
__device__ __align__(16) int2 g_edge[MAXE]; // CSR: {src, coef_bits}

// ---------------------------------------------------------------------------
// Pass 1: in-degree histogram.  edge_index is int32.
// ---------------------------------------------------------------------------
__global__ void deg_kernel(const int* __restrict__ ei, int E) {
    int e = blockIdx.x * blockDim.x + threadIdx.x;
    if (e < E) {
        atomicAdd(&g_deg[ei[E + e]], 1);
    }
}

// ---------------------------------------------------------------------------
// Pass 2: single-block exclusive scan over deg -> start, cursor; also deginv.
// shfl-based: per-thread chunk sums -> warp scan -> warp-0 scan -> add back.
// ---------------------------------------------------------------------------
__global__ void scan_kernel(int N) {
    __shared__ int s_wsum[32];
    const int tid  = threadIdx.x;
    const int lane = tid & 31;
    const int wid  = tid >> 5;
    const int CH   = (N + 1023) / 1024;
    const int base = tid * CH;

    int sum = 0;
    for (int j = 0; j < CH; j++) {
        int i = base + j;
        if (i < N) sum += g_deg[i];
    }

    int inc = sum;
    #pragma unroll
    for (int off = 1; off < 32; off <<= 1) {
        int v = __shfl_up_sync(0xFFFFFFFF, inc, off);
        if (lane >= off) inc += v;
    }
    if (lane == 31) s_wsum[wid] = inc;
    __syncthreads();

    if (wid == 0) {
        int w = s_wsum[lane];
        int wi = w;
        #pragma unroll
        for (int off = 1; off < 32; off <<= 1) {
            int v = __shfl_up_sync(0xFFFFFFFF, wi, off);
            if (lane >= off) wi += v;
        }
        s_wsum[lane] = wi - w;   // exclusive warp offsets
    }
    __syncthreads();

    int run = s_wsum[wid] + inc - sum;
    for (int j = 0; j < CH; j++) {
        int i = base + j;
        if (i < N) {
            int d = g_deg[i];
            g_start[i]  = run;
            g_cursor[i] = run;
            g_deginv[i] = rsqrtf((float)d + 1.0f);
            run += d;
        }
    }
}

// ---------------------------------------------------------------------------
// Pass 3: fill CSR buckets. One int atomic + ONE 8B store per edge.
// ---------------------------------------------------------------------------
__global__ void fill_kernel(const int* __restrict__ ei,
                            const float* __restrict__ ew,
                            int E) {
    int e = blockIdx.x * blockDim.x + threadIdx.x;
    if (e < E) {
        int src = ei[e];
        int dst = ei[E + e];
        int pos = atomicAdd(&g_cursor[dst], 1);
        float coef = g_deginv[src] * ew[e];
        g_edge[pos] = make_int2(src, __float_as_int(coef));
    }
}

// ---------------------------------------------------------------------------
// Pass 4: mega kernel — gather (fp32) + residual + GEMM + GELU + LayerNorm.
// Block = 256 threads (8 warps) -> 8 rows.
//  Phase 1: warp w gathers row row0+w; lane l owns cols [4l,4l+4) as float4.
//           Fast path: full 32-edge batches, statically unrolled (max MLP).
//           Also zeros g_deg[row] for the next replay.
//  Phase 2: col = tid&127, half = tid>>7: GEMM over 4 rows.
//  Phase 3: GELU + LN.
// ---------------------------------------------------------------------------
__global__ void mega_kernel(const float* __restrict__ x,
                            const float* __restrict__ W,
                            const float* __restrict__ b,
                            const float* __restrict__ gamma,
                            const float* __restrict__ beta,
                            float* __restrict__ out,
                            int N) {
    __shared__ float s_a[8][D];
    __shared__ int   s_src[8][32];
    __shared__ float s_cf[8][32];
    __shared__ float s_sum[8][4];
    __shared__ float s_sq[8][4];

    const int tid  = threadIdx.x;
    const int wid  = tid >> 5;
    const int lane = tid & 31;
    const int row0 = blockIdx.x * 8;

    // ---- Phase 1: gather own row ----
    {
        const int row = row0 + wid;
        if (row < N) {
            const int s0   = g_start[row];
            const int dcnt = g_deg[row];
            if (lane == 0) g_deg[row] = 0;   // restore invariant for next call

            float4 acc = make_float4(0.f, 0.f, 0.f, 0.f);

            for (int base = 0; base < dcnt; base += 32) {
                int idx = base + lane;
                if (idx < dcnt) {
                    int2 em = g_edge[s0 + idx];
                    s_src[wid][lane] = em.x;
                    s_cf[wid][lane]  = __int_as_float(em.y);
                }
                __syncwarp();

                int m = dcnt - base;
                if (m >= 32) {
                    #pragma unroll
                    for (int k = 0; k < 32; k++) {
                        int   s = s_src[wid][k];
                        float c = s_cf[wid][k];
                        float4 v = reinterpret_cast<const float4*>(
                                       x + (size_t)s * D)[lane];
                        acc.x += v.x * c; acc.y += v.y * c;
                        acc.z += v.z * c; acc.w += v.w * c;
                    }
                } else {
                    for (int k = 0; k < m; k++) {
                        int   s = s_src[wid][k];
                        float c = s_cf[wid][k];
                        float4 v = reinterpret_cast<const float4*>(
                                       x + (size_t)s * D)[lane];
                        acc.x += v.x * c; acc.y += v.y * c;
                        acc.z += v.z * c; acc.w += v.w * c;
                    }
                }
                __syncwarp();
            }

            float di = g_deginv[row];
            float4 xr = reinterpret_cast<const float4*>(x + (size_t)row * D)[lane];
            float* pa = &s_a[wid][lane * 4];
            pa[0] = acc.x * di + xr.x;
            pa[1] = acc.y * di + xr.y;
            pa[2] = acc.z * di + xr.z;
            pa[3] = acc.w * di + xr.w;
        } else {
            float* pa = &s_a[wid][lane * 4];
            pa[0] = pa[1] = pa[2] = pa[3] = 0.f;
        }
    }
    __syncthreads();

    // ---- Phase 2: GEMM ----
    const int col  = tid & 127;
    const int half = tid >> 7;
    const int r0   = half * 4;

    float acc0 = b[col], acc1 = acc0, acc2 = acc0, acc3 = acc0;

    #pragma unroll 8
    for (int k = 0; k < D; k++) {
        float w = W[k * D + col];
        acc0 += s_a[r0 + 0][k] * w;
        acc1 += s_a[r0 + 1][k] * w;
        acc2 += s_a[r0 + 2][k] * w;
        acc3 += s_a[r0 + 3][k] * w;
    }

    float h[4] = {acc0, acc1, acc2, acc3};

    // exact gelu
    #pragma unroll
    for (int r = 0; r < 4; r++) {
        float v = h[r];
        h[r] = 0.5f * v * (1.0f + erff(v * 0.70710678118654752f));
    }

    // ---- Phase 3: LayerNorm ----
    float sum[4], sq[4];
    #pragma unroll
    for (int r = 0; r < 4; r++) { sum[r] = h[r]; sq[r] = h[r] * h[r]; }

    #pragma unroll
    for (int off = 16; off > 0; off >>= 1) {
        #pragma unroll
        for (int r = 0; r < 4; r++) {
            sum[r] += __shfl_xor_sync(0xFFFFFFFF, sum[r], off);
            sq[r]  += __shfl_xor_sync(0xFFFFFFFF, sq[r], off);
        }
    }
    const int wih = (tid >> 5) & 3;
    if (lane == 0) {
        #pragma unroll
        for (int r = 0; r < 4; r++) {
            s_sum[r0 + r][wih] = sum[r];
            s_sq[r0 + r][wih]  = sq[r];
        }
    }
    __syncthreads();

    float g = gamma[col], bt = beta[col];
    #pragma unroll
    for (int r = 0; r < 4; r++) {
        int rr = r0 + r;
        float s = s_sum[rr][0] + s_sum[rr][1] + s_sum[rr][2] + s_sum[rr][3];
        float q = s_sq[rr][0]  + s_sq[rr][1]  + s_sq[rr][2]  + s_sq[rr][3];
        float mu  = s * (1.0f / D);
        float var = q * (1.0f / D) - mu * mu;
        float rstd = rsqrtf(var + 1e-5f);
        int row = row0 + rr;
        if (row < N) {
            out[(size_t)row * D + col] = (h[r] - mu) * rstd * g + bt;
        }
    }
}

// ---------------------------------------------------------------------------
// Launch
// Inputs (metadata order): x, edge_index(int32), edge_weight, W, b, gamma, beta
// ---------------------------------------------------------------------------
extern "C" void kernel_launch(void* const* d_in, const int* in_sizes, int n_in,
                              void* d_out, int out_size) {
    const float* x     = (const float*)d_in[0];
    const int*   ei    = (const int*)d_in[1];
    const float* ew    = (const float*)d_in[2];
    const float* W     = (const float*)d_in[3];
    const float* b     = (const float*)d_in[4];
    const float* gamma = (const float*)d_in[5];
    const float* beta  = (const float*)d_in[6];
    float*       out   = (float*)d_out;

    const int N = in_sizes[0] / D;       // 10000
    const int E = in_sizes[2];           // 640000

    deg_kernel<<<(E + 255) / 256, 256>>>(ei, E);
    scan_kernel<<<1, 1024>>>(N);                       // + deginv + cursors
    fill_kernel<<<(E + 255) / 256, 256>>>(ei, ew, E);
    mega_kernel<<<(N + 7) / 8, 256>>>(x, W, b, gamma, beta, out, N);
}